// round 14
// baseline (speedup 1.0000x reference)
#include <cuda_runtime.h>
#include <cuda_fp16.h>
#include <math.h>
#include <stdint.h>

#define HFD 128
#define WFD 128
#define DFD 512
#define NA  65536
#define MAXDET 512
#define HIDDEN 1024
#define PD 4608          // 3*3*512
#define NBINS 2048
#define MAXCAND 4096
#define SPLIT1 8
#define SPLIT2 8

// ---------------- scratch (device globals; no allocation allowed) ----------
__device__ float    g_scores[NA];
__device__ float    g_topscore[MAXDET];
__device__ int      g_valid[MAXDET];
__device__ float4   g_sel[MAXDET];
__device__ unsigned char g_keep[MAXDET];
__device__ __align__(16) __half g_pooledh[MAXDET * PD];    // A of GEMM1 (fp16)
__device__ __align__(16) __half g_w1h[HIDDEN * PD];        // B of GEMM1 (n-major)
__device__ __align__(16) __half g_w2h[HIDDEN * HIDDEN];    // B of GEMM2 (n-major)
__device__ __align__(16) __half g_h1h[MAXDET * HIDDEN];    // A of GEMM2 (fp16)
__device__ __align__(16) float g_h2[MAXDET * HIDDEN];
__device__ __align__(16) float g_part[SPLIT1 * MAXDET * HIDDEN];  // split-K partials

// ---------------- prep: weight conversion + scores (independent work) --------
// grid (177, 32), block dim3(32, 8).
// blockIdx.x < 176: convW transpose->fp16. blockIdx.x == 176: scores.
__global__ void k_prep(const float* __restrict__ obj,
                       const float* __restrict__ W1, __half* __restrict__ W1h,
                       const float* __restrict__ W2, __half* __restrict__ W2h) {
    if (blockIdx.x == 176) {
        int t = threadIdx.y * 32 + threadIdx.x;           // 0..255
        int base = (blockIdx.y * 256 + t) * 8;            // 8 anchors per thread
        #pragma unroll
        for (int i = 0; i < 8; i++) {
            int a  = base + i;
            int kk = a & 3;
            int pix = a >> 2;                              // ii*WFD + jj
            float o0 = obj[pix * 8 + 2 * kk];
            float o1 = obj[pix * 8 + 2 * kk + 1];
            float mx = fmaxf(o0, o1);
            float e0 = expf(o0 - mx), e1 = expf(o1 - mx);
            g_scores[a] = e1 / (e0 + e1);
        }
        return;
    }
    __shared__ float tile[32][33];
    const float* W;
    __half* Wh;
    int K, kBase;
    if (blockIdx.x < PD / 32) {
        W = W1; Wh = W1h; K = PD; kBase = blockIdx.x * 32;
    } else {
        W = W2; Wh = W2h; K = HIDDEN; kBase = (blockIdx.x - PD / 32) * 32;
    }
    int N = HIDDEN;
    int nBase = blockIdx.y * 32;
    int tx = threadIdx.x, ty = threadIdx.y;   // 32 x 8
    #pragma unroll
    for (int i = 0; i < 4; i++)
        tile[ty + i * 8][tx] = W[(size_t)(kBase + ty + i * 8) * N + nBase + tx];
    __syncthreads();
    #pragma unroll
    for (int i = 0; i < 4; i++) {
        int n = nBase + ty + i * 8;
        int k = kBase + tx;
        Wh[(size_t)n * K + k] = __float2half(tile[tx][ty + i * 8]);
    }
}

// fused: histogram -> cutoff -> compact -> bitonic top-512 -> boxes -> adj -> NMS
__global__ __launch_bounds__(1024) void k_select(const float* __restrict__ reg) {
    __shared__ __align__(16) char pool[MAXCAND * 8];   // 32KB: bins -> cand -> adj
    __shared__ float4 s_sel[MAXDET];                   // 8KB
    __shared__ unsigned char s_validb[MAXDET];
    __shared__ unsigned s_p[256];
    __shared__ unsigned s_cnt, s_cut;
    __shared__ unsigned s_kw[16];

    int t = threadIdx.x;

    // phase 0: histogram of score bits (scores in (0.5, 1.0])
    unsigned* bins = (unsigned*)pool;
    bins[t] = 0u;
    bins[t + 1024] = 0u;
    if (t == 0) s_cnt = 0u;
    __syncthreads();
    #pragma unroll
    for (int i = 0; i < NA / 1024; i++) {
        float s = g_scores[t + i * 1024];
        if (s > 0.5f) {
            unsigned bits = __float_as_uint(s);
            atomicAdd(&bins[(bits - 0x3F000001u) >> 12], 1u);
        }
    }
    __syncthreads();

    // phase 1: cutoff bin
    if (t < 256) {
        unsigned s = 0;
        #pragma unroll
        for (int i = 0; i < 8; i++) s += bins[t * 8 + i];
        s_p[t] = s;
    }
    __syncthreads();
    if (t == 0) {
        unsigned cum = 0;
        int seg;
        for (seg = 255; seg >= 0; seg--) {
            cum += s_p[seg];
            if (cum >= MAXDET) break;
        }
        unsigned cut = 0;
        if (seg >= 0) {
            unsigned cum2 = cum - s_p[seg];
            int b = seg * 8;
            for (int i = seg * 8 + 7; i >= seg * 8; i--) {
                cum2 += bins[i];
                if (cum2 >= MAXDET) { b = i; break; }
            }
            cut = (unsigned)b;
        }
        s_cut = cut;
    }
    __syncthreads();

    // phase 2: compact candidates (pool reused as u64 cand)
    unsigned long long* cand = (unsigned long long*)pool;
    unsigned cut = s_cut;
    __syncthreads();
    #pragma unroll
    for (int i = 0; i < NA / 1024; i++) {
        int a = t + i * 1024;
        float s = g_scores[a];
        if (s > 0.5f) {
            unsigned bits = __float_as_uint(s);
            unsigned bin  = (bits - 0x3F000001u) >> 12;
            if (bin >= cut) {
                unsigned pos = atomicAdd(&s_cnt, 1u);
                if (pos < MAXCAND)
                    cand[pos] = ((unsigned long long)bits << 32)
                              | (unsigned long long)(0xFFFFFFFFu - (unsigned)a);
            }
        }
    }
    __syncthreads();

    unsigned n = s_cnt;
    if (n > MAXCAND) n = MAXCAND;
    int n2 = 1024;
    while (n2 < (int)n) n2 <<= 1;
    for (int i = t; i < n2; i += 1024)
        if (i >= (int)n) cand[i] = 0ull;
    __syncthreads();

    // phase 3: bitonic sort descending
    for (int k = 2; k <= n2; k <<= 1) {
        for (int j = k >> 1; j > 0; j >>= 1) {
            for (int i = t; i < n2; i += 1024) {
                int ixj = i ^ j;
                if (ixj > i) {
                    unsigned long long va = cand[i], vb = cand[ixj];
                    bool swp = ((i & k) == 0) ? (va < vb) : (va > vb);
                    if (swp) { cand[i] = vb; cand[ixj] = va; }
                }
            }
            __syncthreads();
        }
    }

    // phase 4: extract top-512 + unparameterize boxes (anchors analytic)
    if (t < MAXDET) {
        unsigned long long key = cand[t];
        float4 bx = make_float4(0.f, 0.f, 0.f, 0.f);
        float sc = 0.0f;
        int vl = 0;
        if (key != 0ull) {
            unsigned bits = (unsigned)(key >> 32);
            unsigned a    = 0xFFFFFFFFu - (unsigned)(key & 0xFFFFFFFFull);
            sc = __uint_as_float(bits);
            vl = 1;
            int kk = a & 3;
            int jj = (a >> 2) & 127;
            int ii = a >> 9;
            float sz = (float)((kk + 1) * 32);
            const float* r = reg + ((size_t)(ii * WFD + jj)) * 16 + 4 * kk;
            float r0 = r[0], r1 = r[1], r2 = r[2], r3 = r[3];
            float acx = jj * 16.0f + 8.0f;
            float acy = ii * 16.0f + 8.0f;
            float cx = acx + r0 * sz;
            float cy = acy + r1 * sz;
            float w  = sz * expf(r2);
            float h  = sz * expf(r3);
            bx = make_float4(cx - w * 0.5f, cy - h * 0.5f, w, h);
        }
        g_topscore[t] = sc;
        g_valid[t]    = vl;
        g_sel[t]      = bx;
        s_sel[t]      = bx;
        s_validb[t]   = (unsigned char)vl;
    }
    __syncthreads();

    // phase 5: adjacency bitmask (pool reused as unsigned adj[512*16])
    unsigned* adj = (unsigned*)pool;
    #pragma unroll
    for (int q = 0; q < 8; q++) {
        int e = t + q * 1024;      // 0..8191
        int i = e >> 4;
        int w = e & 15;
        float4 bi = s_sel[i];
        float x1i = bi.x, y1i = bi.y;
        float x2i = bi.x + bi.z, y2i = bi.y + bi.w;
        float areai = bi.z * bi.w;
        unsigned mask = 0u;
        int j0 = w * 32;
        for (int jj = 0; jj < 32; jj++) {
            int j = j0 + jj;
            if (j >= i) break;
            float4 bj = s_sel[j];
            float x2j = bj.x + bj.z, y2j = bj.y + bj.w;
            float ix = fminf(x2i, x2j) - fmaxf(x1i, bj.x);
            ix = fmaxf(0.0f, ix);
            float iy = fminf(y2i, y2j) - fmaxf(y1i, bj.y);
            iy = fmaxf(0.0f, iy);
            float inter = ix * iy;
            float areaj = bj.z * bj.w;
            float iou = inter / (areai + areaj - inter + 1e-8f);
            if (iou > 0.3f) mask |= (1u << jj);
        }
        adj[e] = mask;
    }
    __syncthreads();

    // phase 6: sequential NMS scan (warp 0)
    if (t < 32) {
        unsigned kw = 0u;
        for (int i = 0; i < MAXDET; i++) {
            unsigned w = (t < 16) ? adj[i * 16 + t] : 0u;
            bool sup = __any_sync(0xffffffffu, (w & kw) != 0u);
            bool k = (s_validb[i] != 0) && !sup;
            if (t == (i >> 5)) kw |= ((unsigned)k) << (i & 31);
        }
        if (t < 16) s_kw[t] = kw;
    }
    __syncthreads();
    if (t < MAXDET) g_keep[t] = (unsigned char)((s_kw[t >> 5] >> (t & 31)) & 1u);
}

// ROIAlign, float4-vectorized over channels; fp16 output straight into A layout
__global__ __launch_bounds__(128) void k_roialign(const float* __restrict__ feat) {
    int tile = blockIdx.x;
    int m    = blockIdx.y;
    int ty = tile / 3, tx = tile % 3;
    float4 b = g_sel[m];

    int x0[2], x1[2], y0[2], y1[2];
    float wx[2], wy[2];
    #pragma unroll
    for (int p = 0; p < 2; p++) {
        {
            int sx = tx * 2 + p;
            float tt = ((float)sx + 0.5f) / 6.0f;
            float c = (b.x + tt * b.z) / 16.0f - 0.5f;
            c = fminf(fmaxf(c, 0.0f), 127.0f);
            int c0 = (int)floorf(c);
            x0[p] = c0;
            x1[p] = min(c0 + 1, 127);
            wx[p] = c - (float)c0;
        }
        {
            int sy = ty * 2 + p;
            float tt = ((float)sy + 0.5f) / 6.0f;
            float c = (b.y + tt * b.w) / 16.0f - 0.5f;
            c = fminf(fmaxf(c, 0.0f), 127.0f);
            int c0 = (int)floorf(c);
            y0[p] = c0;
            y1[p] = min(c0 + 1, 127);
            wy[p] = c - (float)c0;
        }
    }

    const float4* f4 = (const float4*)feat;
    int c4 = threadIdx.x;                 // 0..127 -> channels 4*c4..4*c4+3
    float4 mv = make_float4(-INFINITY, -INFINITY, -INFINITY, -INFINITY);
    #pragma unroll
    for (int py = 0; py < 2; py++) {
        float w0y = 1.0f - wy[py], w1y = wy[py];
        #pragma unroll
        for (int px = 0; px < 2; px++) {
            float w0x = 1.0f - wx[px], w1x = wx[px];
            float4 f00 = f4[(y0[py] * WFD + x0[px]) * (DFD / 4) + c4];
            float4 f01 = f4[(y0[py] * WFD + x1[px]) * (DFD / 4) + c4];
            float4 f10 = f4[(y1[py] * WFD + x0[px]) * (DFD / 4) + c4];
            float4 f11 = f4[(y1[py] * WFD + x1[px]) * (DFD / 4) + c4];
            float vx = ((f00.x * w0y) * w0x) + ((f01.x * w0y) * w1x)
                     + ((f10.x * w1y) * w0x) + ((f11.x * w1y) * w1x);
            float vy = ((f00.y * w0y) * w0x) + ((f01.y * w0y) * w1x)
                     + ((f10.y * w1y) * w0x) + ((f11.y * w1y) * w1x);
            float vz = ((f00.z * w0y) * w0x) + ((f01.z * w0y) * w1x)
                     + ((f10.z * w1y) * w0x) + ((f11.z * w1y) * w1x);
            float vw = ((f00.w * w0y) * w0x) + ((f01.w * w0y) * w1x)
                     + ((f10.w * w1y) * w0x) + ((f11.w * w1y) * w1x);
            mv.x = fmaxf(mv.x, vx);
            mv.y = fmaxf(mv.y, vy);
            mv.z = fmaxf(mv.z, vz);
            mv.w = fmaxf(mv.w, vw);
        }
    }
    size_t base = (size_t)m * PD + tile * DFD + c4 * 4;
    *(__half2*)(g_pooledh + base)     = __floats2half2_rn(mv.x, mv.y);
    *(__half2*)(g_pooledh + base + 2) = __floats2half2_rn(mv.z, mv.w);
}

// ---------------- fp16 split-K tensor-core GEMM ------------------------------
// 128x128x64 tiles, 256 threads (8 warps 2x4), warp tile 64x32, 3-stage cp.async.
#define BM 128
#define BN 128
#define BK 64
#define PSTR 72             // fp16 elems; 144B rows -> LDSM rows on distinct banks
#define STAGE_H (2 * BM * PSTR)            // halves per stage (A + B) = 18432
#define AB_H    (BM * PSTR)                // halves per matrix per stage = 9216
#define GEMM_SMEM (3 * STAGE_H * 2)        // bytes = 110592

__device__ __forceinline__ void mma_f16(float* d, const unsigned* a,
                                        unsigned b0, unsigned b1) {
    asm volatile(
        "mma.sync.aligned.m16n8k16.row.col.f32.f16.f16.f32 "
        "{%0,%1,%2,%3}, {%4,%5,%6,%7}, {%8,%9}, {%0,%1,%2,%3};"
        : "+f"(d[0]), "+f"(d[1]), "+f"(d[2]), "+f"(d[3])
        : "r"(a[0]), "r"(a[1]), "r"(a[2]), "r"(a[3]), "r"(b0), "r"(b1));
}

__device__ __forceinline__ void ldsm4(unsigned* r, unsigned addr) {
    asm volatile("ldmatrix.sync.aligned.m8n8.x4.shared.b16 {%0,%1,%2,%3}, [%4];"
                 : "=r"(r[0]), "=r"(r[1]), "=r"(r[2]), "=r"(r[3]) : "r"(addr));
}

__global__ __launch_bounds__(256) void k_gemm_f16(
    const __half* __restrict__ A,   // [M][Kc] row-major
    const __half* __restrict__ B,   // [N][Kc] n-major
    float* __restrict__ Cpart,      // [z][MAXDET][N]
    int N, int Kc, int Kchunk) {

    extern __shared__ __half dynsmem[];
    unsigned smemBase = (unsigned)__cvta_generic_to_shared(dynsmem);

    int tid = threadIdx.x;
    int rowBase = blockIdx.y * BM;
    int colBase = blockIdx.x * BN;
    int kBase   = blockIdx.z * Kchunk;
    int w = tid >> 5, lane = tid & 31;
    int wm = w >> 2, wn = w & 3;          // 2 x 4 warp grid; warp tile 64x32
    int l15 = lane & 15, lhi = (lane >> 4) & 1;

    float acc[4][4][4];
    #pragma unroll
    for (int mt = 0; mt < 4; mt++)
        #pragma unroll
        for (int nt = 0; nt < 4; nt++)
            #pragma unroll
            for (int q = 0; q < 4; q++) acc[mt][nt][q] = 0.0f;

    int niter = Kchunk / BK;

    // stage loader: 2048 x 16B chunks (A 1024, B 1024) / 256 threads = 8 each
    #define LOAD_STAGE(st, k0)                                                        \
    {                                                                                 \
        _Pragma("unroll")                                                             \
        for (int ii = 0; ii < 8; ii++) {                                              \
            int i = tid + ii * 256;                                                   \
            int isB = i >> 10, r = (i >> 3) & 127, c = i & 7;                         \
            const __half* src =                                                       \
                (isB ? B + (size_t)(colBase + r) * Kc                                 \
                     : A + (size_t)(rowBase + r) * Kc) + kBase + (k0) + c * 8;        \
            unsigned dst = smemBase +                                                 \
                ((st) * STAGE_H + isB * AB_H + r * PSTR + c * 8) * 2;                 \
            asm volatile("cp.async.cg.shared.global [%0], [%1], 16;\n"                \
                         :: "r"(dst), "l"(src));                                      \
        }                                                                             \
    }

    LOAD_STAGE(0, 0)
    asm volatile("cp.async.commit_group;\n");
    if (niter > 1) { LOAD_STAGE(1, BK) }
    asm volatile("cp.async.commit_group;\n");

    for (int it = 0; it < niter; it++) {
        if (it + 2 < niter) {
            int st = (it + 2) % 3;
            int k0 = (it + 2) * BK;
            LOAD_STAGE(st, k0)
        }
        asm volatile("cp.async.commit_group;\n");
        asm volatile("cp.async.wait_group 2;\n");
        __syncthreads();

        int st = it % 3;
        unsigned aBase = smemBase + (st * STAGE_H + (wm * 64 + l15) * PSTR) * 2
                       + lhi * 16;
        unsigned bBase = smemBase + (st * STAGE_H + AB_H + (wn * 32 + l15) * PSTR) * 2
                       + lhi * 16;

        #pragma unroll
        for (int kk = 0; kk < BK; kk += 16) {
            unsigned af[4][4], b0[4], b1[4];
            #pragma unroll
            for (int mt = 0; mt < 4; mt++)
                ldsm4(af[mt], aBase + (mt * 16 * PSTR) * 2 + kk * 2);
            ldsm4(b0, bBase + kk * 2);
            ldsm4(b1, bBase + (16 * PSTR) * 2 + kk * 2);
            #pragma unroll
            for (int mt = 0; mt < 4; mt++) {
                mma_f16(acc[mt][0], af[mt], b0[0], b0[2]);
                mma_f16(acc[mt][1], af[mt], b0[1], b0[3]);
                mma_f16(acc[mt][2], af[mt], b1[0], b1[2]);
                mma_f16(acc[mt][3], af[mt], b1[1], b1[3]);
            }
        }
        __syncthreads();
    }
    #undef LOAD_STAGE

    // epilogue: raw fp32 partial store
    int lr = lane >> 2, lc2 = (lane & 3) * 2;
    #pragma unroll
    for (int mt = 0; mt < 4; mt++) {
        int row0 = rowBase + wm * 64 + mt * 16 + lr;
        #pragma unroll
        for (int nt = 0; nt < 4; nt++) {
            int col = colBase + wn * 32 + nt * 8 + lc2;
            size_t base = ((size_t)blockIdx.z * MAXDET + row0) * N + col;
            *(float2*)(Cpart + base) = make_float2(acc[mt][nt][0], acc[mt][nt][1]);
            *(float2*)(Cpart + base + 8 * (size_t)N) =
                make_float2(acc[mt][nt][2], acc[mt][nt][3]);
        }
    }
}

// reduce split-K partials for GEMM1: bias + relu -> fp16 h1
__global__ void k_reduce1(const float* __restrict__ b1) {
    int t = blockIdx.x * blockDim.x + threadIdx.x;   // 0..524287
    int m = t >> 10, n = t & 1023;
    float s = 0.0f;
    #pragma unroll
    for (int z = 0; z < SPLIT1; z++)
        s += g_part[((size_t)z * MAXDET + m) * HIDDEN + n];
    float v = fmaxf(s + b1[n], 0.0f);
    g_h1h[(size_t)m * HIDDEN + n] = __float2half(v);
}

// reduce split-K partials for GEMM2: bias + relu -> fp32 h2
__global__ void k_reduce2(const float* __restrict__ b2) {
    int t = blockIdx.x * blockDim.x + threadIdx.x;
    int m = t >> 10, n = t & 1023;
    float s = 0.0f;
    #pragma unroll
    for (int z = 0; z < SPLIT2; z++)
        s += g_part[((size_t)z * MAXDET + m) * HIDDEN + n];
    g_h2[(size_t)m * HIDDEN + n] = fmaxf(s + b2[n], 0.0f);
}

// GEMM3 (512x4x1024) + unparameterize + keep/valid epilogue
__global__ void k_final(const float* __restrict__ W3,
                        const float* __restrict__ b3,
                        float* __restrict__ out) {
    int m = blockIdx.x;
    __shared__ float red[128 * 4];
    float a0 = 0.f, a1 = 0.f, a2 = 0.f, a3 = 0.f;
    const float* h = g_h2 + m * HIDDEN;
    for (int k = threadIdx.x; k < HIDDEN; k += 128) {
        float hv = h[k];
        const float* w = W3 + k * 4;
        a0 += hv * w[0]; a1 += hv * w[1]; a2 += hv * w[2]; a3 += hv * w[3];
    }
    red[threadIdx.x * 4 + 0] = a0;
    red[threadIdx.x * 4 + 1] = a1;
    red[threadIdx.x * 4 + 2] = a2;
    red[threadIdx.x * 4 + 3] = a3;
    __syncthreads();
    for (int s = 64; s > 0; s >>= 1) {
        if (threadIdx.x < (unsigned)s) {
            red[threadIdx.x * 4 + 0] += red[(threadIdx.x + s) * 4 + 0];
            red[threadIdx.x * 4 + 1] += red[(threadIdx.x + s) * 4 + 1];
            red[threadIdx.x * 4 + 2] += red[(threadIdx.x + s) * 4 + 2];
            red[threadIdx.x * 4 + 3] += red[(threadIdx.x + s) * 4 + 3];
        }
        __syncthreads();
    }
    if (threadIdx.x == 0) {
        float d0 = red[0] + b3[0];
        float d1 = red[1] + b3[1];
        float d2 = red[2] + b3[2];
        float d3 = red[3] + b3[3];
        float4 b = g_sel[m];
        bool keep = (g_keep[m] != 0);
        float* o = out + m * 5;
        if (keep) {
            float acx = b.x + b.z * 0.5f;
            float acy = b.y + b.w * 0.5f;
            float cx = acx + d0 * b.z;
            float cy = acy + d1 * b.w;
            float w  = b.z * expf(d2);
            float hh = b.w * expf(d3);
            float sc = g_valid[m] ? g_topscore[m] : 0.0f;
            o[0] = cx - w * 0.5f;
            o[1] = cy - hh * 0.5f;
            o[2] = w;
            o[3] = hh;
            o[4] = sc;
        } else {
            o[0] = 0.f; o[1] = 0.f; o[2] = 0.f; o[3] = 0.f; o[4] = 0.f;
        }
    }
}

// ---------------- launch -----------------------------------------------------

extern "C" void kernel_launch(void* const* d_in, const int* in_sizes, int n_in,
                              void* d_out, int out_size) {
    const float* features = (const float*)d_in[0];
    const float* rpn_obj  = (const float*)d_in[1];
    const float* rpn_reg  = (const float*)d_in[2];
    const float* W1 = (const float*)d_in[4];
    const float* b1 = (const float*)d_in[5];
    const float* W2 = (const float*)d_in[6];
    const float* b2 = (const float*)d_in[7];
    const float* W3 = (const float*)d_in[8];
    const float* b3 = (const float*)d_in[9];
    float* out = (float*)d_out;

    __half *p_pooledh, *p_w1h, *p_w2h, *p_h1h;
    float *p_part;
    cudaGetSymbolAddress((void**)&p_pooledh, g_pooledh);
    cudaGetSymbolAddress((void**)&p_w1h, g_w1h);
    cudaGetSymbolAddress((void**)&p_w2h, g_w2h);
    cudaGetSymbolAddress((void**)&p_h1h, g_h1h);
    cudaGetSymbolAddress((void**)&p_part, g_part);

    cudaFuncSetAttribute(k_gemm_f16, cudaFuncAttributeMaxDynamicSharedMemorySize,
                         GEMM_SMEM);

    k_prep<<<dim3(177, 32), dim3(32, 8)>>>(rpn_obj, W1, p_w1h, W2, p_w2h);   // 0
    k_select<<<1, 1024>>>(rpn_reg);                                          // 1
    k_roialign<<<dim3(9, MAXDET), 128>>>(features);                          // 2
    k_gemm_f16<<<dim3(HIDDEN / BN, MAXDET / BM, SPLIT1), 256, GEMM_SMEM>>>(  // 3
        p_pooledh, p_w1h, p_part, HIDDEN, PD, PD / SPLIT1);
    k_reduce1<<<MAXDET * HIDDEN / 256, 256>>>(b1);                           // 4
    k_gemm_f16<<<dim3(HIDDEN / BN, MAXDET / BM, SPLIT2), 256, GEMM_SMEM>>>(  // 5
        p_h1h, p_w2h, p_part, HIDDEN, HIDDEN, HIDDEN / SPLIT2);
    k_reduce2<<<MAXDET * HIDDEN / 256, 256>>>(b2);                           // 6
    k_final<<<MAXDET, 128>>>(W3, b3, out);                                   // 7
}

// round 15
// speedup vs baseline: 1.5428x; 1.5428x over previous
#include <cuda_runtime.h>
#include <cuda_fp16.h>
#include <math.h>
#include <stdint.h>

#define HFD 128
#define WFD 128
#define DFD 512
#define NA  65536
#define MAXDET 512
#define HIDDEN 1024
#define PD 4608          // 3*3*512
#define NBINS 2048
#define MAXCAND 4096
#define SPLIT1 6
#define SPLIT2 4

// ---------------- scratch (device globals; no allocation allowed) ----------
__device__ float    g_scores[NA];
__device__ float    g_topscore[MAXDET];
__device__ int      g_valid[MAXDET];
__device__ float4   g_sel[MAXDET];
__device__ unsigned char g_keep[MAXDET];
__device__ __align__(16) __half g_pooledh[MAXDET * PD];    // A of GEMM1 (fp16)
__device__ __align__(16) __half g_w1h[HIDDEN * PD];        // B of GEMM1 (n-major)
__device__ __align__(16) __half g_w2h[HIDDEN * HIDDEN];    // B of GEMM2 (n-major)
__device__ __align__(16) __half g_h1h[MAXDET * HIDDEN];    // A of GEMM2 (fp16)
__device__ __align__(16) float g_part[SPLIT1 * MAXDET * HIDDEN];  // split-K partials

// ---------------- prep: weight conversion + scores (independent work) --------
// grid (177, 32), block dim3(32, 8).
// blockIdx.x < 176: convW transpose->fp16. blockIdx.x == 176: scores.
__global__ void k_prep(const float* __restrict__ obj,
                       const float* __restrict__ W1, __half* __restrict__ W1h,
                       const float* __restrict__ W2, __half* __restrict__ W2h) {
    if (blockIdx.x == 176) {
        int t = threadIdx.y * 32 + threadIdx.x;           // 0..255
        int base = (blockIdx.y * 256 + t) * 8;            // 8 anchors per thread
        #pragma unroll
        for (int i = 0; i < 8; i++) {
            int a  = base + i;
            int kk = a & 3;
            int pix = a >> 2;                              // ii*WFD + jj
            float o0 = obj[pix * 8 + 2 * kk];
            float o1 = obj[pix * 8 + 2 * kk + 1];
            float mx = fmaxf(o0, o1);
            float e0 = expf(o0 - mx), e1 = expf(o1 - mx);
            g_scores[a] = e1 / (e0 + e1);
        }
        return;
    }
    __shared__ float tile[32][33];
    const float* W;
    __half* Wh;
    int K, kBase;
    if (blockIdx.x < PD / 32) {
        W = W1; Wh = W1h; K = PD; kBase = blockIdx.x * 32;
    } else {
        W = W2; Wh = W2h; K = HIDDEN; kBase = (blockIdx.x - PD / 32) * 32;
    }
    int N = HIDDEN;
    int nBase = blockIdx.y * 32;
    int tx = threadIdx.x, ty = threadIdx.y;   // 32 x 8
    #pragma unroll
    for (int i = 0; i < 4; i++)
        tile[ty + i * 8][tx] = W[(size_t)(kBase + ty + i * 8) * N + nBase + tx];
    __syncthreads();
    #pragma unroll
    for (int i = 0; i < 4; i++) {
        int n = nBase + ty + i * 8;
        int k = kBase + tx;
        Wh[(size_t)n * K + k] = __float2half(tile[tx][ty + i * 8]);
    }
}

// fused: histogram -> cutoff -> compact -> bitonic top-512 -> boxes -> adj -> NMS
__global__ __launch_bounds__(1024) void k_select(const float* __restrict__ reg) {
    __shared__ __align__(16) char pool[MAXCAND * 8];   // 32KB: bins -> cand -> adj
    __shared__ float4 s_sel[MAXDET];                   // 8KB
    __shared__ unsigned char s_validb[MAXDET];
    __shared__ unsigned s_p[256];
    __shared__ unsigned s_cnt, s_cut;
    __shared__ unsigned s_kw[16];

    int t = threadIdx.x;

    // phase 0: histogram of score bits (scores in (0.5, 1.0])
    unsigned* bins = (unsigned*)pool;
    bins[t] = 0u;
    bins[t + 1024] = 0u;
    if (t == 0) s_cnt = 0u;
    __syncthreads();
    #pragma unroll
    for (int i = 0; i < NA / 1024; i++) {
        float s = g_scores[t + i * 1024];
        if (s > 0.5f) {
            unsigned bits = __float_as_uint(s);
            atomicAdd(&bins[(bits - 0x3F000001u) >> 12], 1u);
        }
    }
    __syncthreads();

    // phase 1: cutoff bin
    if (t < 256) {
        unsigned s = 0;
        #pragma unroll
        for (int i = 0; i < 8; i++) s += bins[t * 8 + i];
        s_p[t] = s;
    }
    __syncthreads();
    if (t == 0) {
        unsigned cum = 0;
        int seg;
        for (seg = 255; seg >= 0; seg--) {
            cum += s_p[seg];
            if (cum >= MAXDET) break;
        }
        unsigned cut = 0;
        if (seg >= 0) {
            unsigned cum2 = cum - s_p[seg];
            int b = seg * 8;
            for (int i = seg * 8 + 7; i >= seg * 8; i--) {
                cum2 += bins[i];
                if (cum2 >= MAXDET) { b = i; break; }
            }
            cut = (unsigned)b;
        }
        s_cut = cut;
    }
    __syncthreads();

    // phase 2: compact candidates (pool reused as u64 cand)
    unsigned long long* cand = (unsigned long long*)pool;
    unsigned cut = s_cut;
    __syncthreads();
    #pragma unroll
    for (int i = 0; i < NA / 1024; i++) {
        int a = t + i * 1024;
        float s = g_scores[a];
        if (s > 0.5f) {
            unsigned bits = __float_as_uint(s);
            unsigned bin  = (bits - 0x3F000001u) >> 12;
            if (bin >= cut) {
                unsigned pos = atomicAdd(&s_cnt, 1u);
                if (pos < MAXCAND)
                    cand[pos] = ((unsigned long long)bits << 32)
                              | (unsigned long long)(0xFFFFFFFFu - (unsigned)a);
            }
        }
    }
    __syncthreads();

    unsigned n = s_cnt;
    if (n > MAXCAND) n = MAXCAND;
    int n2 = 1024;
    while (n2 < (int)n) n2 <<= 1;
    for (int i = t; i < n2; i += 1024)
        if (i >= (int)n) cand[i] = 0ull;
    __syncthreads();

    // phase 3: bitonic sort descending
    for (int k = 2; k <= n2; k <<= 1) {
        for (int j = k >> 1; j > 0; j >>= 1) {
            for (int i = t; i < n2; i += 1024) {
                int ixj = i ^ j;
                if (ixj > i) {
                    unsigned long long va = cand[i], vb = cand[ixj];
                    bool swp = ((i & k) == 0) ? (va < vb) : (va > vb);
                    if (swp) { cand[i] = vb; cand[ixj] = va; }
                }
            }
            __syncthreads();
        }
    }

    // phase 4: extract top-512 + unparameterize boxes (anchors analytic)
    if (t < MAXDET) {
        unsigned long long key = cand[t];
        float4 bx = make_float4(0.f, 0.f, 0.f, 0.f);
        float sc = 0.0f;
        int vl = 0;
        if (key != 0ull) {
            unsigned bits = (unsigned)(key >> 32);
            unsigned a    = 0xFFFFFFFFu - (unsigned)(key & 0xFFFFFFFFull);
            sc = __uint_as_float(bits);
            vl = 1;
            int kk = a & 3;
            int jj = (a >> 2) & 127;
            int ii = a >> 9;
            float sz = (float)((kk + 1) * 32);
            const float* r = reg + ((size_t)(ii * WFD + jj)) * 16 + 4 * kk;
            float r0 = r[0], r1 = r[1], r2 = r[2], r3 = r[3];
            float acx = jj * 16.0f + 8.0f;
            float acy = ii * 16.0f + 8.0f;
            float cx = acx + r0 * sz;
            float cy = acy + r1 * sz;
            float w  = sz * expf(r2);
            float h  = sz * expf(r3);
            bx = make_float4(cx - w * 0.5f, cy - h * 0.5f, w, h);
        }
        g_topscore[t] = sc;
        g_valid[t]    = vl;
        g_sel[t]      = bx;
        s_sel[t]      = bx;
        s_validb[t]   = (unsigned char)vl;
    }
    __syncthreads();

    // phase 5: adjacency bitmask (pool reused as unsigned adj[512*16])
    unsigned* adj = (unsigned*)pool;
    #pragma unroll
    for (int q = 0; q < 8; q++) {
        int e = t + q * 1024;      // 0..8191
        int i = e >> 4;
        int w = e & 15;
        float4 bi = s_sel[i];
        float x1i = bi.x, y1i = bi.y;
        float x2i = bi.x + bi.z, y2i = bi.y + bi.w;
        float areai = bi.z * bi.w;
        unsigned mask = 0u;
        int j0 = w * 32;
        for (int jj = 0; jj < 32; jj++) {
            int j = j0 + jj;
            if (j >= i) break;
            float4 bj = s_sel[j];
            float x2j = bj.x + bj.z, y2j = bj.y + bj.w;
            float ix = fminf(x2i, x2j) - fmaxf(x1i, bj.x);
            ix = fmaxf(0.0f, ix);
            float iy = fminf(y2i, y2j) - fmaxf(y1i, bj.y);
            iy = fmaxf(0.0f, iy);
            float inter = ix * iy;
            float areaj = bj.z * bj.w;
            float iou = inter / (areai + areaj - inter + 1e-8f);
            if (iou > 0.3f) mask |= (1u << jj);
        }
        adj[e] = mask;
    }
    __syncthreads();

    // phase 6: sequential NMS scan (warp 0)
    if (t < 32) {
        unsigned kw = 0u;
        for (int i = 0; i < MAXDET; i++) {
            unsigned w = (t < 16) ? adj[i * 16 + t] : 0u;
            bool sup = __any_sync(0xffffffffu, (w & kw) != 0u);
            bool k = (s_validb[i] != 0) && !sup;
            if (t == (i >> 5)) kw |= ((unsigned)k) << (i & 31);
        }
        if (t < 16) s_kw[t] = kw;
    }
    __syncthreads();
    if (t < MAXDET) g_keep[t] = (unsigned char)((s_kw[t >> 5] >> (t & 31)) & 1u);
}

// ROIAlign, float4-vectorized over channels; fp16 output straight into A layout
__global__ __launch_bounds__(128) void k_roialign(const float* __restrict__ feat) {
    int tile = blockIdx.x;
    int m    = blockIdx.y;
    int ty = tile / 3, tx = tile % 3;
    float4 b = g_sel[m];

    int x0[2], x1[2], y0[2], y1[2];
    float wx[2], wy[2];
    #pragma unroll
    for (int p = 0; p < 2; p++) {
        {
            int sx = tx * 2 + p;
            float tt = ((float)sx + 0.5f) / 6.0f;
            float c = (b.x + tt * b.z) / 16.0f - 0.5f;
            c = fminf(fmaxf(c, 0.0f), 127.0f);
            int c0 = (int)floorf(c);
            x0[p] = c0;
            x1[p] = min(c0 + 1, 127);
            wx[p] = c - (float)c0;
        }
        {
            int sy = ty * 2 + p;
            float tt = ((float)sy + 0.5f) / 6.0f;
            float c = (b.y + tt * b.w) / 16.0f - 0.5f;
            c = fminf(fmaxf(c, 0.0f), 127.0f);
            int c0 = (int)floorf(c);
            y0[p] = c0;
            y1[p] = min(c0 + 1, 127);
            wy[p] = c - (float)c0;
        }
    }

    const float4* f4 = (const float4*)feat;
    int c4 = threadIdx.x;                 // 0..127 -> channels 4*c4..4*c4+3
    float4 mv = make_float4(-INFINITY, -INFINITY, -INFINITY, -INFINITY);
    #pragma unroll
    for (int py = 0; py < 2; py++) {
        float w0y = 1.0f - wy[py], w1y = wy[py];
        #pragma unroll
        for (int px = 0; px < 2; px++) {
            float w0x = 1.0f - wx[px], w1x = wx[px];
            float4 f00 = f4[(y0[py] * WFD + x0[px]) * (DFD / 4) + c4];
            float4 f01 = f4[(y0[py] * WFD + x1[px]) * (DFD / 4) + c4];
            float4 f10 = f4[(y1[py] * WFD + x0[px]) * (DFD / 4) + c4];
            float4 f11 = f4[(y1[py] * WFD + x1[px]) * (DFD / 4) + c4];
            float vx = ((f00.x * w0y) * w0x) + ((f01.x * w0y) * w1x)
                     + ((f10.x * w1y) * w0x) + ((f11.x * w1y) * w1x);
            float vy = ((f00.y * w0y) * w0x) + ((f01.y * w0y) * w1x)
                     + ((f10.y * w1y) * w0x) + ((f11.y * w1y) * w1x);
            float vz = ((f00.z * w0y) * w0x) + ((f01.z * w0y) * w1x)
                     + ((f10.z * w1y) * w0x) + ((f11.z * w1y) * w1x);
            float vw = ((f00.w * w0y) * w0x) + ((f01.w * w0y) * w1x)
                     + ((f10.w * w1y) * w0x) + ((f11.w * w1y) * w1x);
            mv.x = fmaxf(mv.x, vx);
            mv.y = fmaxf(mv.y, vy);
            mv.z = fmaxf(mv.z, vz);
            mv.w = fmaxf(mv.w, vw);
        }
    }
    size_t base = (size_t)m * PD + tile * DFD + c4 * 4;
    *(__half2*)(g_pooledh + base)     = __floats2half2_rn(mv.x, mv.y);
    *(__half2*)(g_pooledh + base + 2) = __floats2half2_rn(mv.z, mv.w);
}

// ---------------- fp16 split-K tensor-core GEMM (r13 geometry) ---------------
// Cpart[z] = A[64-row band] @ B[64-col band]^T over K chunk z.
// 64x64x64 tiles, 256 threads (8 warps, 2x4), warp tile 32x16, ldmatrix feeds.
#define BM 64
#define BN 64
#define BK 64
#define PSTR 72   // fp16 elems; 144B rows -> LDSM rows on distinct banks

__device__ __forceinline__ void mma_f16(float* d, const unsigned* a,
                                        unsigned b0, unsigned b1) {
    asm volatile(
        "mma.sync.aligned.m16n8k16.row.col.f32.f16.f16.f32 "
        "{%0,%1,%2,%3}, {%4,%5,%6,%7}, {%8,%9}, {%0,%1,%2,%3};"
        : "+f"(d[0]), "+f"(d[1]), "+f"(d[2]), "+f"(d[3])
        : "r"(a[0]), "r"(a[1]), "r"(a[2]), "r"(a[3]), "r"(b0), "r"(b1));
}

__device__ __forceinline__ void ldsm4(unsigned* r, unsigned addr) {
    asm volatile("ldmatrix.sync.aligned.m8n8.x4.shared.b16 {%0,%1,%2,%3}, [%4];"
                 : "=r"(r[0]), "=r"(r[1]), "=r"(r[2]), "=r"(r[3]) : "r"(addr));
}

__global__ __launch_bounds__(256) void k_gemm_f16(
    const __half* __restrict__ A,   // [M][Kc] row-major
    const __half* __restrict__ B,   // [N][Kc] n-major
    float* __restrict__ Cpart,      // [z][MAXDET][N]
    int N, int Kc, int Kchunk) {

    __shared__ __half sA[2][BM * PSTR];
    __shared__ __half sB[2][BN * PSTR];

    int tid = threadIdx.x;
    int rowBase = blockIdx.y * BM;
    int colBase = blockIdx.x * BN;
    int kBase   = blockIdx.z * Kchunk;
    int w = tid >> 5, lane = tid & 31;
    int wm = w >> 2, wn = w & 3;          // 2 x 4 warp grid; warp tile 32x16
    int l15 = lane & 15, lhi = (lane >> 4) & 1;

    float acc[2][2][4];
    #pragma unroll
    for (int mt = 0; mt < 2; mt++)
        #pragma unroll
        for (int nt = 0; nt < 2; nt++)
            #pragma unroll
            for (int q = 0; q < 4; q++) acc[mt][nt][q] = 0.0f;

    unsigned sAb[2] = {(unsigned)__cvta_generic_to_shared(&sA[0][0]),
                       (unsigned)__cvta_generic_to_shared(&sA[1][0])};
    unsigned sBb[2] = {(unsigned)__cvta_generic_to_shared(&sB[0][0]),
                       (unsigned)__cvta_generic_to_shared(&sB[1][0])};

    int niter = Kchunk / BK;

    #define LOAD_STAGE(st, k0)                                                        \
    {                                                                                 \
        _Pragma("unroll")                                                             \
        for (int ii = 0; ii < 4; ii++) {                                              \
            int i = tid + ii * 256;                                                   \
            int isB = i >> 9, r = (i >> 3) & 63, c = i & 7;                           \
            const __half* src =                                                       \
                (isB ? B + (size_t)(colBase + r) * Kc                                 \
                     : A + (size_t)(rowBase + r) * Kc) + kBase + (k0) + c * 8;        \
            unsigned dst = (isB ? sBb[st] : sAb[st]) + (r * PSTR + c * 8) * 2;        \
            asm volatile("cp.async.cg.shared.global [%0], [%1], 16;\n"                \
                         :: "r"(dst), "l"(src));                                      \
        }                                                                             \
    }

    LOAD_STAGE(0, 0)
    asm volatile("cp.async.commit_group;\n");

    for (int it = 0; it < niter; it++) {
        if (it + 1 < niter) {
            int st = (it + 1) & 1;
            int k0 = (it + 1) * BK;
            LOAD_STAGE(st, k0)
        }
        asm volatile("cp.async.commit_group;\n");
        asm volatile("cp.async.wait_group 1;\n");
        __syncthreads();

        int st = it & 1;
        unsigned aBase = sAb[st] + ((wm * 32 + l15) * PSTR) * 2 + lhi * 16;
        unsigned bBase = sBb[st] + ((wn * 16 + l15) * PSTR) * 2 + lhi * 16;

        #pragma unroll
        for (int kk = 0; kk < BK; kk += 16) {
            unsigned a0[4], a1[4], bb[4];
            ldsm4(a0, aBase + kk * 2);
            ldsm4(a1, aBase + 16 * PSTR * 2 + kk * 2);
            ldsm4(bb, bBase + kk * 2);
            mma_f16(acc[0][0], a0, bb[0], bb[2]);
            mma_f16(acc[0][1], a0, bb[1], bb[3]);
            mma_f16(acc[1][0], a1, bb[0], bb[2]);
            mma_f16(acc[1][1], a1, bb[1], bb[3]);
        }
        __syncthreads();
    }
    #undef LOAD_STAGE

    int lr = lane >> 2, lc2 = (lane & 3) * 2;
    #pragma unroll
    for (int mt = 0; mt < 2; mt++) {
        int row0 = rowBase + wm * 32 + mt * 16 + lr;
        #pragma unroll
        for (int nt = 0; nt < 2; nt++) {
            int col = colBase + wn * 16 + nt * 8 + lc2;
            size_t base = ((size_t)blockIdx.z * MAXDET + row0) * N + col;
            *(float2*)(Cpart + base) = make_float2(acc[mt][nt][0], acc[mt][nt][1]);
            *(float2*)(Cpart + base + 8 * (size_t)N) =
                make_float2(acc[mt][nt][2], acc[mt][nt][3]);
        }
    }
}

// reduce split-K partials for GEMM1: bias + relu -> fp16 h1
__global__ void k_reduce1(const float* __restrict__ b1) {
    int t = blockIdx.x * blockDim.x + threadIdx.x;   // 0..524287
    int m = t >> 10, n = t & 1023;
    float s = 0.0f;
    #pragma unroll
    for (int z = 0; z < SPLIT1; z++)
        s += g_part[((size_t)z * MAXDET + m) * HIDDEN + n];
    float v = fmaxf(s + b1[n], 0.0f);
    g_h1h[(size_t)m * HIDDEN + n] = __float2half(v);
}

// fused: reduce GEMM2 partials (bias+relu) + GEMM3 (512x4x1024) + epilogue
__global__ void k_final(const float* __restrict__ b2,
                        const float* __restrict__ W3,
                        const float* __restrict__ b3,
                        float* __restrict__ out) {
    int m = blockIdx.x;
    __shared__ float red[128 * 4];
    float a0 = 0.f, a1 = 0.f, a2 = 0.f, a3 = 0.f;
    const float* p0 = g_part + (size_t)m * HIDDEN;
    for (int k = threadIdx.x; k < HIDDEN; k += 128) {
        float s = 0.0f;
        #pragma unroll
        for (int z = 0; z < SPLIT2; z++)
            s += p0[(size_t)z * MAXDET * HIDDEN + k];
        float hv = fmaxf(s + b2[k], 0.0f);
        const float* w = W3 + k * 4;
        a0 += hv * w[0]; a1 += hv * w[1]; a2 += hv * w[2]; a3 += hv * w[3];
    }
    red[threadIdx.x * 4 + 0] = a0;
    red[threadIdx.x * 4 + 1] = a1;
    red[threadIdx.x * 4 + 2] = a2;
    red[threadIdx.x * 4 + 3] = a3;
    __syncthreads();
    for (int s = 64; s > 0; s >>= 1) {
        if (threadIdx.x < (unsigned)s) {
            red[threadIdx.x * 4 + 0] += red[(threadIdx.x + s) * 4 + 0];
            red[threadIdx.x * 4 + 1] += red[(threadIdx.x + s) * 4 + 1];
            red[threadIdx.x * 4 + 2] += red[(threadIdx.x + s) * 4 + 2];
            red[threadIdx.x * 4 + 3] += red[(threadIdx.x + s) * 4 + 3];
        }
        __syncthreads();
    }
    if (threadIdx.x == 0) {
        float d0 = red[0] + b3[0];
        float d1 = red[1] + b3[1];
        float d2 = red[2] + b3[2];
        float d3 = red[3] + b3[3];
        float4 b = g_sel[m];
        bool keep = (g_keep[m] != 0);
        float* o = out + m * 5;
        if (keep) {
            float acx = b.x + b.z * 0.5f;
            float acy = b.y + b.w * 0.5f;
            float cx = acx + d0 * b.z;
            float cy = acy + d1 * b.w;
            float w  = b.z * expf(d2);
            float hh = b.w * expf(d3);
            float sc = g_valid[m] ? g_topscore[m] : 0.0f;
            o[0] = cx - w * 0.5f;
            o[1] = cy - hh * 0.5f;
            o[2] = w;
            o[3] = hh;
            o[4] = sc;
        } else {
            o[0] = 0.f; o[1] = 0.f; o[2] = 0.f; o[3] = 0.f; o[4] = 0.f;
        }
    }
}

// ---------------- launch -----------------------------------------------------

extern "C" void kernel_launch(void* const* d_in, const int* in_sizes, int n_in,
                              void* d_out, int out_size) {
    const float* features = (const float*)d_in[0];
    const float* rpn_obj  = (const float*)d_in[1];
    const float* rpn_reg  = (const float*)d_in[2];
    const float* W1 = (const float*)d_in[4];
    const float* b1 = (const float*)d_in[5];
    const float* W2 = (const float*)d_in[6];
    const float* b2 = (const float*)d_in[7];
    const float* W3 = (const float*)d_in[8];
    const float* b3 = (const float*)d_in[9];
    float* out = (float*)d_out;

    __half *p_pooledh, *p_w1h, *p_w2h, *p_h1h;
    float *p_part;
    cudaGetSymbolAddress((void**)&p_pooledh, g_pooledh);
    cudaGetSymbolAddress((void**)&p_w1h, g_w1h);
    cudaGetSymbolAddress((void**)&p_w2h, g_w2h);
    cudaGetSymbolAddress((void**)&p_h1h, g_h1h);
    cudaGetSymbolAddress((void**)&p_part, g_part);

    k_prep<<<dim3(177, 32), dim3(32, 8)>>>(rpn_obj, W1, p_w1h, W2, p_w2h);   // 0
    k_select<<<1, 1024>>>(rpn_reg);                                          // 1
    k_roialign<<<dim3(9, MAXDET), 128>>>(features);                          // 2
    k_gemm_f16<<<dim3(HIDDEN / BN, MAXDET / BM, SPLIT1), 256>>>(             // 3
        p_pooledh, p_w1h, p_part, HIDDEN, PD, PD / SPLIT1);
    k_reduce1<<<MAXDET * HIDDEN / 256, 256>>>(b1);                           // 4
    k_gemm_f16<<<dim3(HIDDEN / BN, MAXDET / BM, SPLIT2), 256>>>(             // 5
        p_h1h, p_w2h, p_part, HIDDEN, HIDDEN, HIDDEN / SPLIT2);
    k_final<<<MAXDET, 128>>>(b2, W3, b3, out);                               // 6
}